// round 1
// baseline (speedup 1.0000x reference)
#include <cuda_runtime.h>
#include <math.h>

// ---------------------------------------------------------------------------
// MS-SSIM loss, 10 channels of 1024x1024 fp32, 5 pyramid levels.
// Separable 11x11 gaussian, fused 5-conv tiled SSIM kernel per level.
// ---------------------------------------------------------------------------

#define WINR 5           // window radius (11 taps)
#define TSZ 32           // output tile (32x32)
#define HALO 42          // TSZ + 10
#define NCH 10

__device__ float g_sim_acc[50];   // [level][channel]
__device__ float g_cs_acc[50];

// scratch pyramid: levels 1..4 for p and t
// 10*(512^2 + 256^2 + 128^2 + 64^2) = 3,481,600 floats each
#define SCR_TOTAL 3481600
__device__ float g_scr_p[SCR_TOTAL];
__device__ float g_scr_t[SCR_TOTAL];

__global__ void zero_acc_kernel() {
    int i = threadIdx.x;
    if (i < 50) { g_sim_acc[i] = 0.f; g_cs_acc[i] = 0.f; }
}

__device__ __forceinline__ void make_gauss(float g[11]) {
    float s = 0.f;
#pragma unroll
    for (int k = 0; k < 11; k++) {
        float x = (float)(k - 5);
        g[k] = expf(-(x * x) / 4.5f);   // 2*sigma^2 = 4.5
        s += g[k];
    }
    float inv = 1.f / s;
#pragma unroll
    for (int k = 0; k < 11; k++) g[k] *= inv;
}

// Fused separable SSIM kernel. If P==nullptr, read from scratch at `off`.
__global__ __launch_bounds__(256)
void ssim_kernel(const float* __restrict__ Pin, const float* __restrict__ Tin,
                 int off, int H, int level)
{
    const float* P = Pin ? Pin : (const float*)(g_scr_p + off);
    const float* T = Tin ? Tin : (const float*)(g_scr_t + off);
    const int W = H;
    const int OH = H - 10;

    __shared__ float sp[HALO][44];
    __shared__ float st[HALO][44];
    __shared__ float hs[5][HALO][33];   // hp, ht, hpp, htt, hpt
    __shared__ float rs[8], rc[8];

    float g[11];
    make_gauss(g);

    const int ch = blockIdx.z;
    const float* Pc = P + (size_t)ch * H * W;
    const float* Tc = T + (size_t)ch * H * W;
    const int by = blockIdx.y * TSZ;
    const int bx = blockIdx.x * TSZ;
    const int tid = threadIdx.y * 32 + threadIdx.x;

    // load halo tile
    for (int i = tid; i < HALO * HALO; i += 256) {
        int r = i / HALO, c = i % HALO;
        int gy = by + r, gx = bx + c;
        float pv = 0.f, tv = 0.f;
        if (gy < H && gx < W) {
            size_t idx = (size_t)gy * W + gx;
            pv = Pc[idx];
            tv = Tc[idx];
        }
        sp[r][c] = pv;
        st[r][c] = tv;
    }
    __syncthreads();

    // horizontal pass: 42 rows x 32 output cols, 5 quantities
    for (int i = tid; i < HALO * TSZ; i += 256) {
        int r = i / TSZ, c = i % TSZ;
        float a0 = 0.f, a1 = 0.f, a2 = 0.f, a3 = 0.f, a4 = 0.f;
#pragma unroll
        for (int k = 0; k < 11; k++) {
            float w = g[k];
            float pv = sp[r][c + k];
            float tv = st[r][c + k];
            a0 += w * pv;
            a1 += w * tv;
            a2 += w * pv * pv;
            a3 += w * tv * tv;
            a4 += w * pv * tv;
        }
        hs[0][r][c] = a0;
        hs[1][r][c] = a1;
        hs[2][r][c] = a2;
        hs[3][r][c] = a3;
        hs[4][r][c] = a4;
    }
    __syncthreads();

    // vertical pass + SSIM stats
    const float C1v = 0.01f * 0.01f;
    const float C2v = 0.03f * 0.03f;
    float lsim = 0.f, lcs = 0.f;
    const int tx = threadIdx.x;
#pragma unroll
    for (int j = 0; j < 4; j++) {
        int ty = threadIdx.y + j * 8;
        int oy = by + ty, ox = bx + tx;
        if (oy < OH && ox < OH) {
            float m1 = 0.f, m2 = 0.f, spp = 0.f, stt = 0.f, spt = 0.f;
#pragma unroll
            for (int k = 0; k < 11; k++) {
                float w = g[k];
                m1  += w * hs[0][ty + k][tx];
                m2  += w * hs[1][ty + k][tx];
                spp += w * hs[2][ty + k][tx];
                stt += w * hs[3][ty + k][tx];
                spt += w * hs[4][ty + k][tx];
            }
            float m1s = m1 * m1, m2s = m2 * m2, m12 = m1 * m2;
            float s1 = spp - m1s, s2 = stt - m2s, s12 = spt - m12;
            float v1 = 2.f * s12 + C2v;
            float v2 = s1 + s2 + C2v;
            float cs = v1 / v2;
            float sim = ((2.f * m12 + C1v) * v1) / ((m1s + m2s + C1v) * v2);
            lcs += cs;
            lsim += sim;
        }
    }

    // warp reduce then block reduce
#pragma unroll
    for (int o = 16; o > 0; o >>= 1) {
        lsim += __shfl_down_sync(0xffffffff, lsim, o);
        lcs  += __shfl_down_sync(0xffffffff, lcs, o);
    }
    if (threadIdx.x == 0) { rs[threadIdx.y] = lsim; rc[threadIdx.y] = lcs; }
    __syncthreads();
    if (tid == 0) {
        float ss = 0.f, cc = 0.f;
#pragma unroll
        for (int i = 0; i < 8; i++) { ss += rs[i]; cc += rc[i]; }
        atomicAdd(&g_sim_acc[level * NCH + ch], ss);
        atomicAdd(&g_cs_acc[level * NCH + ch], cc);
    }
}

// 2x2 average pool. If inP==nullptr, read from scratch at in_off.
// Output always goes to scratch at out_off.
__global__ void pool_kernel(const float* __restrict__ inPp,
                            const float* __restrict__ inTp,
                            int in_off, int out_off, int Ho)
{
    const float* inP = inPp ? inPp : (const float*)(g_scr_p + in_off);
    const float* inT = inTp ? inTp : (const float*)(g_scr_t + in_off);
    float* outP = g_scr_p + out_off;
    float* outT = g_scr_t + out_off;
    const int Wo = Ho;
    const int Hi = 2 * Ho;
    const int n = NCH * Ho * Wo;
    for (int idx = blockIdx.x * blockDim.x + threadIdx.x; idx < n;
         idx += gridDim.x * blockDim.x) {
        int c = idx / (Ho * Wo);
        int rem = idx - c * (Ho * Wo);
        int y = rem / Wo, x = rem - y * Wo;
        size_t base = (size_t)c * Hi * Hi + (size_t)(2 * y) * Hi + 2 * x;
        outP[idx] = 0.25f * (inP[base] + inP[base + 1] + inP[base + Hi] + inP[base + Hi + 1]);
        outT[idx] = 0.25f * (inT[base] + inT[base + 1] + inT[base + Hi] + inT[base + Hi + 1]);
    }
}

__global__ void combine_kernel(float* out)
{
    if (threadIdx.x == 0 && blockIdx.x == 0) {
        const double w[5]  = {0.0448, 0.2856, 0.3001, 0.2363, 0.1333};
        const double cnt[5] = {1014.0 * 1014.0, 502.0 * 502.0, 246.0 * 246.0,
                               118.0 * 118.0, 54.0 * 54.0};
        double total = 0.0;
        for (int c = 0; c < NCH; c++) {
            double ms4 = (double)g_sim_acc[4 * NCH + c] / cnt[4];
            double p2  = pow(ms4, w[4]);
            double pc  = 1.0;
            for (int l = 0; l < 4; l++) {
                double mc = (double)g_cs_acc[l * NCH + c] / cnt[l];
                pc *= pow(mc, w[l]) * p2;
            }
            total += pc;
        }
        out[0] = (float)(1.0 - total);
    }
}

extern "C" void kernel_launch(void* const* d_in, const int* in_sizes, int n_in,
                              void* d_out, int out_size)
{
    const float* P = (const float*)d_in[0];
    const float* T = (const float*)d_in[1];
    float* out = (float*)d_out;

    zero_acc_kernel<<<1, 64>>>();

    // level geometry
    int H = 1024;
    const float* curP = P;   // nullptr => scratch
    const float* curT = T;
    int cur_off = 0;
    int next_off = 0;

    for (int l = 0; l < 5; l++) {
        int OH = H - 10;
        dim3 grid((OH + TSZ - 1) / TSZ, (OH + TSZ - 1) / TSZ, NCH);
        dim3 blk(32, 8);
        ssim_kernel<<<grid, blk>>>(curP, curT, cur_off, H, l);

        if (l < 4) {
            int Ho = H / 2;
            int n = NCH * Ho * Ho;
            int nb = (n + 255) / 256;
            if (nb > 16384) nb = 16384;
            pool_kernel<<<nb, 256>>>(curP, curT, cur_off, next_off, Ho);
            curP = nullptr;
            curT = nullptr;
            cur_off = next_off;
            next_off += n;
            H = Ho;
        }
    }

    combine_kernel<<<1, 1>>>(out);
}

// round 3
// speedup vs baseline: 1.5125x; 1.5125x over previous
#include <cuda_runtime.h>
#include <math.h>

// ---------------------------------------------------------------------------
// MS-SSIM loss. 10 channels 1024x1024 fp32, 5 levels.
// Separable 11-tap gaussian, register-sliding-window conv, f32x2 packed FMA.
// ---------------------------------------------------------------------------

#define NCH 10
#define TX 32     // output tile width
#define TY 54     // output tile height

// normalized gaussian, sigma=1.5, 11 taps (compile-time constants)
__device__ constexpr float GW[11] = {
    0.00102842f, 0.00759877f, 0.03600077f, 0.10936076f, 0.21300535f,
    0.26601172f,
    0.21300535f, 0.10936076f, 0.03600077f, 0.00759877f, 0.00102842f};

__device__ float g_sim_acc[50];   // [level][channel]
__device__ float g_cs_acc[50];

#define SCR_TOTAL 3481600
__device__ __align__(16) float g_scr_p[SCR_TOTAL];
__device__ __align__(16) float g_scr_t[SCR_TOTAL];

__global__ void zero_acc_kernel() {
    int i = threadIdx.x;
    if (i < 50) { g_sim_acc[i] = 0.f; g_cs_acc[i] = 0.f; }
}

// ---- f32x2 packed math helpers (Blackwell) --------------------------------
typedef unsigned long long ull;

__device__ __forceinline__ ull pk2(float a, float b) {
    ull r; asm("mov.b64 %0, {%1, %2};" : "=l"(r) : "f"(a), "f"(b)); return r;
}
__device__ __forceinline__ void upk2(ull v, float& a, float& b) {
    asm("mov.b64 {%0, %1}, %2;" : "=f"(a), "=f"(b) : "l"(v));
}
#define FMA2(d, a, b, c) \
    asm("fma.rn.f32x2 %0, %1, %2, %3;" : "=l"(d) : "l"(a), "l"(b), "l"(c))
#define MUL2(d, a, b) \
    asm("mul.rn.f32x2 %0, %1, %2;" : "=l"(d) : "l"(a), "l"(b))

// ---------------------------------------------------------------------------
// Fused separable SSIM kernel.
//  Stage A (horizontal): 256 threads; thread t handles halo-row r=t/4 and 8
//  consecutive output columns c0=(t%4)*8. Raw data loaded as float4 directly
//  from global; 5 conv quantities accumulated in registers (packed),
//  written to SMEM.
//  Stage B (vertical): thread t handles column tx=t%32 and 7 consecutive
//  output rows; sliding window over 17 SMEM rows.
// ---------------------------------------------------------------------------
__global__ __launch_bounds__(256, 3)
void ssim_kernel(const float* __restrict__ Pin, const float* __restrict__ Tin,
                 int off, int H, int level)
{
    const float* P = Pin ? Pin : (const float*)(g_scr_p + off);
    const float* T = Tin ? Tin : (const float*)(g_scr_t + off);
    const int W = H;
    const int OH = H - 10;

    // 66 rows: rows 64,65 are never written, only read by discarded outputs
    __shared__ float2 hs01[66][33];
    __shared__ float2 hs23[66][33];
    __shared__ float  hs4 [66][33];
    __shared__ float rs[8], rc[8];

    const int ch = blockIdx.z;
    const float* Pc = P + (size_t)ch * H * W;
    const float* Tc = T + (size_t)ch * H * W;
    const int by = blockIdx.y * TY;
    const int bx = blockIdx.x * TX;
    const int t  = threadIdx.x;

    // packed weights (w,w)
    ull W2[11];
#pragma unroll
    for (int i = 0; i < 11; i++) W2[i] = pk2(GW[i], GW[i]);

    // ---------------- Stage A: horizontal pass ----------------
    {
        const int r  = t >> 2;          // 0..63
        const int c0 = (t & 3) * 8;     // 0,8,16,24
        const int gy = by + r;
        const bool rowok = gy < H;
        const float* rowP = Pc + (size_t)gy * W + bx + c0;
        const float* rowT = Tc + (size_t)gy * W + bx + c0;

        ull s01[8], s23[8];
        float s4[8];
#pragma unroll
        for (int j = 0; j < 8; j++) { s01[j] = 0ULL; s23[j] = 0ULL; s4[j] = 0.f; }

#pragma unroll
        for (int chk = 0; chk < 5; chk++) {
            float4 pv4 = make_float4(0.f, 0.f, 0.f, 0.f);
            float4 tv4 = make_float4(0.f, 0.f, 0.f, 0.f);
            int gx = bx + c0 + chk * 4;
            if (rowok && gx < W) {
                pv4 = *(const float4*)(rowP + chk * 4);
                tv4 = *(const float4*)(rowT + chk * 4);
            }
            const float pa[4] = {pv4.x, pv4.y, pv4.z, pv4.w};
            const float ta[4] = {tv4.x, tv4.y, tv4.z, tv4.w};
#pragma unroll
            for (int q = 0; q < 4; q++) {
                const int k = chk * 4 + q;
                if (k < 18) {
                    float pv = pa[q], tv = ta[q];
                    ull ptp = pk2(pv, tv);
                    ull sqp; MUL2(sqp, ptp, ptp);
                    float ptv = pv * tv;
#pragma unroll
                    for (int j = 0; j < 8; j++) {
                        const int i = k - j;
                        if (i >= 0 && i <= 10) {
                            FMA2(s01[j], W2[i], ptp, s01[j]);
                            FMA2(s23[j], W2[i], sqp, s23[j]);
                            s4[j] = fmaf(GW[i], ptv, s4[j]);
                        }
                    }
                }
            }
        }
#pragma unroll
        for (int j = 0; j < 8; j++) {
            float a, b;
            upk2(s01[j], a, b); hs01[r][c0 + j] = make_float2(a, b);
            upk2(s23[j], a, b); hs23[r][c0 + j] = make_float2(a, b);
            hs4[r][c0 + j] = s4[j];
        }
    }
    __syncthreads();

    // ---------------- Stage B: vertical pass + SSIM ----------------
    const float C1v = 0.01f * 0.01f;
    const float C2v = 0.03f * 0.03f;
    float lsim = 0.f, lcs = 0.f;
    {
        const int tx = t & 31;
        const int g  = t >> 5;          // 0..7
        const int r0 = g * 7;           // rows r0..r0+6 (last group: 5 valid)
        const int cnt = (54 - r0) < 7 ? (54 - r0) : 7;
        const int ox = bx + tx;

        ull a01[7], a23[7];
        float a4[7];
#pragma unroll
        for (int j = 0; j < 7; j++) { a01[j] = 0ULL; a23[j] = 0ULL; a4[j] = 0.f; }

#pragma unroll
        for (int k = 0; k < 17; k++) {
            float2 h01 = hs01[r0 + k][tx];
            float2 h23 = hs23[r0 + k][tx];
            float  h4  = hs4 [r0 + k][tx];
            ull h01p = pk2(h01.x, h01.y);
            ull h23p = pk2(h23.x, h23.y);
#pragma unroll
            for (int j = 0; j < 7; j++) {
                const int i = k - j;
                if (i >= 0 && i <= 10) {
                    FMA2(a01[j], W2[i], h01p, a01[j]);
                    FMA2(a23[j], W2[i], h23p, a23[j]);
                    a4[j] = fmaf(GW[i], h4, a4[j]);
                }
            }
        }

#pragma unroll
        for (int j = 0; j < 7; j++) {
            int oy = by + r0 + j;
            if (j < cnt && oy < OH && ox < OH) {
                float m1, m2, spp, stt;
                upk2(a01[j], m1, m2);
                upk2(a23[j], spp, stt);
                float spt = a4[j];
                float m1s = m1 * m1, m2s = m2 * m2, m12 = m1 * m2;
                float s1 = spp - m1s, s2 = stt - m2s, s12 = spt - m12;
                float v1 = 2.f * s12 + C2v;
                float v2 = s1 + s2 + C2v;
                float cs  = __fdividef(v1, v2);
                float sim = __fdividef((2.f * m12 + C1v) * v1,
                                       (m1s + m2s + C1v) * v2);
                lcs  += cs;
                lsim += sim;
            }
        }
    }

    // block reduce + atomic
#pragma unroll
    for (int o = 16; o > 0; o >>= 1) {
        lsim += __shfl_down_sync(0xffffffff, lsim, o);
        lcs  += __shfl_down_sync(0xffffffff, lcs, o);
    }
    if ((t & 31) == 0) { rs[t >> 5] = lsim; rc[t >> 5] = lcs; }
    __syncthreads();
    if (t == 0) {
        float ss = 0.f, cc = 0.f;
#pragma unroll
        for (int i = 0; i < 8; i++) { ss += rs[i]; cc += rc[i]; }
        atomicAdd(&g_sim_acc[level * NCH + ch], ss);
        atomicAdd(&g_cs_acc[level * NCH + ch], cc);
    }
}

// ---------------------------------------------------------------------------
// 2x2 avg pool: float4 in, float2 out, shift/mask indexing (all pow2).
// ---------------------------------------------------------------------------
__global__ __launch_bounds__(256)
void pool_kernel(const float* __restrict__ inPp, const float* __restrict__ inTp,
                 int in_off, int out_off, int Wi, int shiftRow, int shiftCh)
{
    const float* inP = inPp ? inPp : (const float*)(g_scr_p + in_off);
    const float* inT = inTp ? inTp : (const float*)(g_scr_t + in_off);
    float* outP = g_scr_p + out_off;
    float* outT = g_scr_t + out_off;

    int idx = blockIdx.x * 256 + threadIdx.x;
    int c   = idx >> shiftCh;
    int rem = idx & ((1 << shiftCh) - 1);
    int y   = rem >> shiftRow;
    int xp  = rem & ((1 << shiftRow) - 1);

    size_t ibase = (size_t)c * Wi * Wi + (size_t)(2 * y) * Wi + 4 * xp;
    float4 a = *(const float4*)(inP + ibase);
    float4 b = *(const float4*)(inP + ibase + Wi);
    float4 e = *(const float4*)(inT + ibase);
    float4 f = *(const float4*)(inT + ibase + Wi);

    float2 op, ot;
    op.x = 0.25f * (a.x + a.y + b.x + b.y);
    op.y = 0.25f * (a.z + a.w + b.z + b.w);
    ot.x = 0.25f * (e.x + e.y + f.x + f.y);
    ot.y = 0.25f * (e.z + e.w + f.z + f.w);

    *(float2*)(outP + 2 * (size_t)idx) = op;
    *(float2*)(outT + 2 * (size_t)idx) = ot;
}

// ---------------------------------------------------------------------------
__global__ void combine_kernel(float* out)
{
    if (threadIdx.x == 0 && blockIdx.x == 0) {
        const double w[5]   = {0.0448, 0.2856, 0.3001, 0.2363, 0.1333};
        const double cnt[5] = {1014.0 * 1014.0, 502.0 * 502.0, 246.0 * 246.0,
                               118.0 * 118.0, 54.0 * 54.0};
        double total = 0.0;
        for (int c = 0; c < NCH; c++) {
            double ms4 = (double)g_sim_acc[4 * NCH + c] / cnt[4];
            double p2  = pow(ms4, w[4]);
            double pc  = 1.0;
            for (int l = 0; l < 4; l++) {
                double mc = (double)g_cs_acc[l * NCH + c] / cnt[l];
                pc *= pow(mc, w[l]) * p2;
            }
            total += pc;
        }
        out[0] = (float)(1.0 - total);
    }
}

extern "C" void kernel_launch(void* const* d_in, const int* in_sizes, int n_in,
                              void* d_out, int out_size)
{
    const float* P = (const float*)d_in[0];
    const float* T = (const float*)d_in[1];
    float* out = (float*)d_out;

    zero_acc_kernel<<<1, 64>>>();

    int H = 1024;
    const float* curP = P;   // nullptr => scratch
    const float* curT = T;
    int cur_off = 0;
    int next_off = 0;

    for (int l = 0; l < 5; l++) {
        int OH = H - 10;
        dim3 grid((OH + TX - 1) / TX, (OH + TY - 1) / TY, NCH);
        ssim_kernel<<<grid, 256>>>(curP, curT, cur_off, H, l);

        if (l < 4) {
            int Ho = H / 2;
            int n = NCH * Ho * Ho;
            int n_pairs = n / 2;
            int shiftRow = 0; while ((1 << shiftRow) != Ho / 2) shiftRow++;
            int shiftCh = 0;  while ((1 << shiftCh) != Ho * (Ho / 2)) shiftCh++;
            pool_kernel<<<n_pairs / 256, 256>>>(curP, curT, cur_off, next_off,
                                                H, shiftRow, shiftCh);
            curP = nullptr;
            curT = nullptr;
            cur_off = next_off;
            next_off += n;
            H = Ho;
        }
    }

    combine_kernel<<<1, 1>>>(out);
}

// round 4
// speedup vs baseline: 1.6295x; 1.0774x over previous
#include <cuda_runtime.h>
#include <math.h>

// ---------------------------------------------------------------------------
// MS-SSIM loss. 10 channels 1024x1024 fp32, 5 levels.
// Separable 11-tap gaussian, register-sliding-window conv, f32x2 packed FMA,
// fused 2x2 avg-pool, offset-by-0.5 trick for variance cancellation.
// ---------------------------------------------------------------------------

#define NCH 10
#define TX 32     // output tile width
#define TY 54     // output tile height

// normalized gaussian, sigma=1.5, 11 taps
__device__ constexpr float GW[11] = {
    0.00102842f, 0.00759877f, 0.03600077f, 0.10936076f, 0.21300535f,
    0.26601172f,
    0.21300535f, 0.10936076f, 0.03600077f, 0.00759877f, 0.00102842f};

__device__ float g_sim_acc[50];   // [level][channel]
__device__ float g_cs_acc[50];

#define SCR_TOTAL 3481600
__device__ __align__(16) float g_scr_p[SCR_TOTAL];
__device__ __align__(16) float g_scr_t[SCR_TOTAL];

// ---- f32x2 packed math helpers (Blackwell) --------------------------------
typedef unsigned long long ull;

__device__ __forceinline__ ull pk2(float a, float b) {
    ull r; asm("mov.b64 %0, {%1, %2};" : "=l"(r) : "f"(a), "f"(b)); return r;
}
__device__ __forceinline__ void upk2(ull v, float& a, float& b) {
    asm("mov.b64 {%0, %1}, %2;" : "=f"(a), "=f"(b) : "l"(v));
}
#define FMA2(d, a, b, c) \
    asm("fma.rn.f32x2 %0, %1, %2, %3;" : "=l"(d) : "l"(a), "l"(b), "l"(c))
#define MUL2(d, a, b) \
    asm("mul.rn.f32x2 %0, %1, %2;" : "=l"(d) : "l"(a), "l"(b))

// ---------------------------------------------------------------------------
// Fused separable SSIM + pool kernel. Data in "offset space" (x - 0.5):
// level 0 subtracts sub=0.5 at load; pool writes offset values to scratch, so
// deeper levels pass sub=0. Sigma terms are shift-invariant; means get +0.5
// added back for the luminance term.
// ---------------------------------------------------------------------------
__global__ __launch_bounds__(256, 3)
void ssim_kernel(const float* __restrict__ Pin, const float* __restrict__ Tin,
                 int off, int H, int level, int out_off, int do_pool, float sub)
{
    const float* P = Pin ? Pin : (const float*)(g_scr_p + off);
    const float* T = Tin ? Tin : (const float*)(g_scr_t + off);
    const int W = H;
    const int OH = H - 10;

    __shared__ float2 hs01[66][33];
    __shared__ float2 hs23[66][33];
    __shared__ float  hs4 [66][33];
    __shared__ float rs[8], rc[8];

    const int ch = blockIdx.z;
    const float* Pc = P + (size_t)ch * H * W;
    const float* Tc = T + (size_t)ch * H * W;
    const int by = blockIdx.y * TY;
    const int bx = blockIdx.x * TX;
    const int t  = threadIdx.x;

    ull W2[11];
#pragma unroll
    for (int i = 0; i < 11; i++) W2[i] = pk2(GW[i], GW[i]);

    // ---------------- Stage A: horizontal pass + fused pool ----------------
    {
        const int r  = t >> 2;          // 0..63
        const int c0 = (t & 3) * 8;     // 0,8,16,24
        const int gy = by + r;
        const bool rowok = gy < H;
        const float* rowP = Pc + (size_t)gy * W + bx + c0;
        const float* rowT = Tc + (size_t)gy * W + bx + c0;

        ull s01[8], s23[8];
        float s4[8];
        float plP[4], plT[4];   // horizontal 2-sums for pool (chunks 0,1)
#pragma unroll
        for (int j = 0; j < 8; j++) { s01[j] = 0ULL; s23[j] = 0ULL; s4[j] = 0.f; }

#pragma unroll
        for (int chk = 0; chk < 5; chk++) {
            float4 pv4 = make_float4(0.f, 0.f, 0.f, 0.f);
            float4 tv4 = make_float4(0.f, 0.f, 0.f, 0.f);
            int gx = bx + c0 + chk * 4;
            if (rowok && gx < W) {
                pv4 = *(const float4*)(rowP + chk * 4);
                tv4 = *(const float4*)(rowT + chk * 4);
            }
            pv4.x -= sub; pv4.y -= sub; pv4.z -= sub; pv4.w -= sub;
            tv4.x -= sub; tv4.y -= sub; tv4.z -= sub; tv4.w -= sub;

            if (chk < 2) {
                plP[chk * 2 + 0] = pv4.x + pv4.y;
                plP[chk * 2 + 1] = pv4.z + pv4.w;
                plT[chk * 2 + 0] = tv4.x + tv4.y;
                plT[chk * 2 + 1] = tv4.z + tv4.w;
            }

            const float pa[4] = {pv4.x, pv4.y, pv4.z, pv4.w};
            const float ta[4] = {tv4.x, tv4.y, tv4.z, tv4.w};
#pragma unroll
            for (int q = 0; q < 4; q++) {
                const int k = chk * 4 + q;
                if (k < 18) {
                    float pv = pa[q], tv = ta[q];
                    ull ptp = pk2(pv, tv);
                    ull sqp; MUL2(sqp, ptp, ptp);
                    float ptv = pv * tv;
#pragma unroll
                    for (int j = 0; j < 8; j++) {
                        const int i = k - j;
                        if (i >= 0 && i <= 10) {
                            FMA2(s01[j], W2[i], ptp, s01[j]);
                            FMA2(s23[j], W2[i], sqp, s23[j]);
                            s4[j] = fmaf(GW[i], ptv, s4[j]);
                        }
                    }
                }
            }

            // pool write once chunks 0,1 are in (row pair via shfl: r <-> r+1
            // are lanes +-4 within the same warp; by is even so gy parity == r
            // parity).
            if (chk == 1 && do_pool) {
                float vp[4], vt[4];
#pragma unroll
                for (int q = 0; q < 4; q++) {
                    vp[q] = plP[q] + __shfl_down_sync(0xffffffffu, plP[q], 4);
                    vt[q] = plT[q] + __shfl_down_sync(0xffffffffu, plT[q], 4);
                }
                if (((r & 1) == 0) && (gy + 1 < H)) {
                    const int Ho = H >> 1;
                    size_t o = (size_t)ch * Ho * Ho + (size_t)(gy >> 1) * Ho
                               + ((bx + c0) >> 1);
                    *(float4*)(g_scr_p + out_off + o) =
                        make_float4(0.25f * vp[0], 0.25f * vp[1],
                                    0.25f * vp[2], 0.25f * vp[3]);
                    *(float4*)(g_scr_t + out_off + o) =
                        make_float4(0.25f * vt[0], 0.25f * vt[1],
                                    0.25f * vt[2], 0.25f * vt[3]);
                }
            }
        }
#pragma unroll
        for (int j = 0; j < 8; j++) {
            float a, b;
            upk2(s01[j], a, b); hs01[r][c0 + j] = make_float2(a, b);
            upk2(s23[j], a, b); hs23[r][c0 + j] = make_float2(a, b);
            hs4[r][c0 + j] = s4[j];
        }
    }
    __syncthreads();

    // ---------------- Stage B: vertical pass + SSIM ----------------
    const float C1v = 0.01f * 0.01f;
    const float C2v = 0.03f * 0.03f;
    float lsim = 0.f, lcs = 0.f;
    {
        const int tx = t & 31;
        const int g  = t >> 5;          // 0..7
        const int r0 = g * 7;
        const int cnt = (54 - r0) < 7 ? (54 - r0) : 7;
        const int ox = bx + tx;

        ull a01[7], a23[7];
        float a4[7];
#pragma unroll
        for (int j = 0; j < 7; j++) { a01[j] = 0ULL; a23[j] = 0ULL; a4[j] = 0.f; }

#pragma unroll
        for (int k = 0; k < 17; k++) {
            float2 h01 = hs01[r0 + k][tx];
            float2 h23 = hs23[r0 + k][tx];
            float  h4  = hs4 [r0 + k][tx];
            ull h01p = pk2(h01.x, h01.y);
            ull h23p = pk2(h23.x, h23.y);
#pragma unroll
            for (int j = 0; j < 7; j++) {
                const int i = k - j;
                if (i >= 0 && i <= 10) {
                    FMA2(a01[j], W2[i], h01p, a01[j]);
                    FMA2(a23[j], W2[i], h23p, a23[j]);
                    a4[j] = fmaf(GW[i], h4, a4[j]);
                }
            }
        }

#pragma unroll
        for (int j = 0; j < 7; j++) {
            int oy = by + r0 + j;
            if (j < cnt && oy < OH && ox < OH) {
                float m1o, m2o, spp, stt;
                upk2(a01[j], m1o, m2o);
                upk2(a23[j], spp, stt);
                float spt = a4[j];
                // sigmas: shift-invariant, tiny terms -> no cancellation blowup
                float s1  = spp - m1o * m1o;
                float s2  = stt - m2o * m2o;
                float s12 = spt - m1o * m2o;
                // real means for luminance
                float m1 = m1o + 0.5f, m2 = m2o + 0.5f;
                float m1s = m1 * m1, m2s = m2 * m2, m12 = m1 * m2;
                float v1 = 2.f * s12 + C2v;
                float v2 = s1 + s2 + C2v;
                float cs  = __fdividef(v1, v2);
                float sim = cs * __fdividef(2.f * m12 + C1v, m1s + m2s + C1v);
                lcs  += cs;
                lsim += sim;
            }
        }
    }

    // block reduce + atomic
#pragma unroll
    for (int o = 16; o > 0; o >>= 1) {
        lsim += __shfl_down_sync(0xffffffff, lsim, o);
        lcs  += __shfl_down_sync(0xffffffff, lcs, o);
    }
    if ((t & 31) == 0) { rs[t >> 5] = lsim; rc[t >> 5] = lcs; }
    __syncthreads();
    if (t == 0) {
        float ss = 0.f, cc = 0.f;
#pragma unroll
        for (int i = 0; i < 8; i++) { ss += rs[i]; cc += rc[i]; }
        atomicAdd(&g_sim_acc[level * NCH + ch], ss);
        atomicAdd(&g_cs_acc[level * NCH + ch], cc);
    }
}

// ---------------------------------------------------------------------------
__global__ void combine_kernel(float* out)
{
    if (threadIdx.x == 0 && blockIdx.x == 0) {
        const double w[5]   = {0.0448, 0.2856, 0.3001, 0.2363, 0.1333};
        const double cnt[5] = {1014.0 * 1014.0, 502.0 * 502.0, 246.0 * 246.0,
                               118.0 * 118.0, 54.0 * 54.0};
        double total = 0.0;
        for (int c = 0; c < NCH; c++) {
            double ms4 = (double)g_sim_acc[4 * NCH + c] / cnt[4];
            double p2  = pow(ms4, w[4]);
            double pc  = 1.0;
            for (int l = 0; l < 4; l++) {
                double mc = (double)g_cs_acc[l * NCH + c] / cnt[l];
                pc *= pow(mc, w[l]) * p2;
            }
            total += pc;
        }
        out[0] = (float)(1.0 - total);
        // reset accumulators for the next replay (globals start zeroed)
        for (int i = 0; i < 50; i++) { g_sim_acc[i] = 0.f; g_cs_acc[i] = 0.f; }
    }
}

extern "C" void kernel_launch(void* const* d_in, const int* in_sizes, int n_in,
                              void* d_out, int out_size)
{
    const float* P = (const float*)d_in[0];
    const float* T = (const float*)d_in[1];
    float* out = (float*)d_out;

    int H = 1024;
    const float* curP = P;   // nullptr => scratch
    const float* curT = T;
    int cur_off = 0;
    int next_off = 0;

    for (int l = 0; l < 5; l++) {
        int OH = H - 10;
        dim3 grid((OH + TX - 1) / TX, (OH + TY - 1) / TY, NCH);
        int do_pool = (l < 4) ? 1 : 0;
        float sub = (l == 0) ? 0.5f : 0.0f;
        ssim_kernel<<<grid, 256>>>(curP, curT, cur_off, H, l,
                                   next_off, do_pool, sub);
        if (l < 4) {
            int Ho = H / 2;
            curP = nullptr;
            curT = nullptr;
            cur_off = next_off;
            next_off += NCH * Ho * Ho;
            H = Ho;
        }
    }

    combine_kernel<<<1, 1>>>(out);
}